// round 14
// baseline (speedup 1.0000x reference)
#include <cuda_runtime.h>
#include <cuda_bf16.h>
#include <cstdint>

// y[n] = tanh(W[t_n] @ x[n] + b[t_n]);  N=131072, D=64, 256 types (int32).
// 1) k_bucket: single-pass bucketing by type (block-aggregated atomics).
// 2) k_compute: per (type, 128-atom tile) CTA, 256 threads, HMMA bf16
//    m16n8k16 with split-bf16 (hi+lo, 3 chained MMAs), ldmatrix loads.
//    W columns are PERMUTED at staging so each thread owns 16 contiguous
//    output columns -> epilogue is 8x STG.128 (optimal sectors).
// Counters self-reset (last CTA per type), so state is all-zero every replay.

#define D 64
#define MAX_N 131072
#define TILE 128
#define CAP 1024          // bucket capacity per type
#define MAX_TILES 6       // 768 slots covered by grid; overflow via stride loop
#define BBLK 256
#define XPB 144           // smem pitch bytes; 144%128==16 -> ldmatrix conflict-free

__device__ int g_cnt[256];
__device__ int g_done[256];
__device__ int g_perm[256 * CAP];

// ------------------------------------------------------------------ sort ----
__global__ void k_bucket(const int* __restrict__ types, int n)
{
    __shared__ int sh_cnt[256];
    __shared__ int sh_base[256];
    const int g = blockIdx.x, tid = threadIdx.x;
    sh_cnt[tid] = 0;
    __syncthreads();

    const int chunk = (n + BBLK - 1) / BBLK;
    const int lo = g * chunk, hi = min(n, lo + chunk);

    int tcache[4];
    int cnt = 0;
    for (int i = lo + tid; i < hi; i += blockDim.x) {
        int t = types[i] & 255;
        tcache[cnt++] = t;
        atomicAdd(&sh_cnt[t], 1);
    }
    __syncthreads();

    const int c = sh_cnt[tid];
    sh_base[tid] = tid * CAP + ((c > 0) ? atomicAdd(&g_cnt[tid], c) : 0);
    __syncthreads();

    cnt = 0;
    for (int i = lo + tid; i < hi; i += blockDim.x) {
        int t = tcache[cnt++];
        int dst = atomicAdd(&sh_base[t], 1);
        g_perm[dst] = i;
    }
}

// --------------------------------------------------------------- helpers ----
__device__ __forceinline__ uint32_t smem_u32(const void* p) {
    uint32_t a;
    asm("{ .reg .u64 t; cvta.to.shared.u64 t, %1; cvt.u32.u64 %0, t; }"
        : "=r"(a) : "l"(p));
    return a;
}
__device__ __forceinline__ float tanh_fast(float x) {
    float r;
    asm("tanh.approx.f32 %0, %1;" : "=f"(r) : "f"(x));
    return r;
}
__device__ __forceinline__ void ldsm4(uint32_t* r, uint32_t addr) {
    asm volatile("ldmatrix.sync.aligned.m8n8.x4.shared.b16 {%0,%1,%2,%3}, [%4];"
                 : "=r"(r[0]), "=r"(r[1]), "=r"(r[2]), "=r"(r[3]) : "r"(addr));
}
__device__ __forceinline__ void mma16816(float* c, const uint32_t* a,
                                         uint32_t b0, uint32_t b1)
{
    asm volatile(
        "mma.sync.aligned.m16n8k16.row.col.f32.bf16.bf16.f32 "
        "{%0,%1,%2,%3}, {%4,%5,%6,%7}, {%8,%9}, {%0,%1,%2,%3};"
        : "+f"(c[0]), "+f"(c[1]), "+f"(c[2]), "+f"(c[3])
        : "r"(a[0]), "r"(a[1]), "r"(a[2]), "r"(a[3]), "r"(b0), "r"(b1));
}
__device__ __forceinline__ void cvt_split(float4 v, uint2& hi, uint2& lo)
{
    __nv_bfloat162 h01 = __floats2bfloat162_rn(v.x, v.y);
    __nv_bfloat162 h23 = __floats2bfloat162_rn(v.z, v.w);
    __nv_bfloat162 l01 = __floats2bfloat162_rn(
        v.x - __bfloat162float(h01.x), v.y - __bfloat162float(h01.y));
    __nv_bfloat162 l23 = __floats2bfloat162_rn(
        v.z - __bfloat162float(h23.x), v.w - __bfloat162float(h23.y));
    hi = make_uint2(*(uint32_t*)&h01, *(uint32_t*)&h23);
    lo = make_uint2(*(uint32_t*)&l01, *(uint32_t*)&l23);
}

// ------------------------------------------------------------- compute ----
#define SM_SP    0
#define SM_BIAS  512
#define SM_XHI   768
#define SM_XLO   (SM_XHI + TILE * XPB)
#define SM_WHI   (SM_XLO + TILE * XPB)
#define SM_WLO   (SM_WHI + 64 * XPB)
#define SM_TOTAL (SM_WLO + 64 * XPB)     // 56064 bytes
#define DXL      (SM_XLO - SM_XHI)
#define DWL      (SM_WLO - SM_WHI)

__global__ __launch_bounds__(256)
void k_compute(const float* __restrict__ x,
               const float* __restrict__ W,
               const float* __restrict__ b,
               float* __restrict__ out)
{
    extern __shared__ char smem[];
    const int t    = blockIdx.x;
    const int tile = blockIdx.y;
    const int tid  = threadIdx.x;

    // Read this type's count; last CTA of the type resets counters.
    __shared__ int s_end;
    if (tid == 0) {
        int e = *((volatile int*)&g_cnt[t]);
        __threadfence();
        if (atomicAdd(&g_done[t], 1) == MAX_TILES - 1) {
            g_done[t] = 0;
            g_cnt[t]  = 0;
            __threadfence();
        }
        s_end = e;
    }
    __syncthreads();
    const int cnt_t = s_end;

    int*   sp    = (int*)(smem + SM_SP);
    float* sbias = (float*)(smem + SM_BIAS);

    const int wid = tid >> 5, lane = tid & 31;
    const int gq = lane >> 2, tig = lane & 3;
    const uint32_t sb = smem_u32(smem);

    const uint32_t aAddr = sb + SM_XHI +
        (wid * 16 + (lane & 7) + ((lane >> 3) & 1) * 8) * XPB +
        ((lane >> 4) & 1) * 16;
    const uint32_t bAddr = sb + SM_WHI +
        ((lane & 7) + ((lane >> 4) & 1) * 8) * XPB +
        ((lane >> 3) & 1) * 16;

    for (int base_l = tile * TILE; base_l < cnt_t; base_l += MAX_TILES * TILE) {

        if (tid < TILE)
            sp[tid] = (base_l + tid < cnt_t) ? g_perm[t * CAP + base_l + tid] : -1;
        if (tid >= 192) sbias[tid - 192] = b[(size_t)t * 64 + (tid - 192)];
        __syncthreads();

        // Stage X tile (fp32 -> bf16 hi+lo), pitch 144B.
#pragma unroll
        for (int i = 0; i < 8; i++) {
            int idx = tid + i * 256;
            int row = idx >> 4, c4 = idx & 15;
            int a = sp[row];
            if (a >= 0) {
                float4 v = reinterpret_cast<const float4*>(x + (size_t)a * D)[c4];
                uint2 hi, lo;
                cvt_split(v, hi, lo);
                char* p = smem + SM_XHI + row * XPB + c4 * 8;
                *(uint2*)p         = hi;
                *(uint2*)(p + DXL) = lo;
            }
        }
        // Stage W[t] with column permutation: gmem W row o -> smem row
        // n = 8*((o&15)>>1) + 2*(o>>4) + (o&1), so the MMA n-index maps
        // thread (tig) to output cols [16*tig, 16*tig+16).
        const float4* Wt = reinterpret_cast<const float4*>(W + (size_t)t * D * D);
#pragma unroll
        for (int i = 0; i < 4; i++) {
            int idx = tid + i * 256;
            int o = idx >> 4, c4 = idx & 15;
            int rW = 8 * ((o & 15) >> 1) + 2 * (o >> 4) + (o & 1);
            uint2 hi, lo;
            cvt_split(Wt[idx], hi, lo);
            char* p = smem + SM_WHI + rW * XPB + c4 * 8;
            *(uint2*)p         = hi;
            *(uint2*)(p + DWL) = lo;
        }
        __syncthreads();

        float acc[8][4];
#pragma unroll
        for (int nt = 0; nt < 8; nt++)
#pragma unroll
            for (int r = 0; r < 4; r++) acc[nt][r] = 0.f;

#pragma unroll
        for (int k = 0; k < 4; k++) {
            uint32_t ah[4], al[4];
            ldsm4(ah, aAddr + k * 32);
            ldsm4(al, aAddr + k * 32 + DXL);
#pragma unroll
            for (int p = 0; p < 4; p++) {
                uint32_t bh[4], bl[4];
                uint32_t pb = bAddr + p * (16 * XPB) + k * 32;
                ldsm4(bh, pb);
                ldsm4(bl, pb + DWL);
                mma16816(acc[2 * p],     ah, bh[0], bh[1]);
                mma16816(acc[2 * p],     al, bh[0], bh[1]);
                mma16816(acc[2 * p],     ah, bl[0], bl[1]);
                mma16816(acc[2 * p + 1], ah, bh[2], bh[3]);
                mma16816(acc[2 * p + 1], al, bh[2], bh[3]);
                mma16816(acc[2 * p + 1], ah, bl[2], bl[3]);
            }
        }

        // Epilogue: thread owns output cols [16*tig, 16*tig+16).
        // acc[nt][2h+e] = (row wid*16 + h*8 + gq, col 16*tig + 2*nt + e).
        const float4* bb = reinterpret_cast<const float4*>(sbias + 16 * tig);
        float4 br0 = bb[0], br1 = bb[1], br2 = bb[2], br3 = bb[3];
#pragma unroll
        for (int h = 0; h < 2; h++) {
            const int r = wid * 16 + h * 8 + gq;
            const int a = sp[r];
            if (a < 0) continue;
            float4* op = reinterpret_cast<float4*>(out + (size_t)a * D + 16 * tig);
            float4 y;
            y.x = tanh_fast(acc[0][2 * h]     + br0.x);
            y.y = tanh_fast(acc[0][2 * h + 1] + br0.y);
            y.z = tanh_fast(acc[1][2 * h]     + br0.z);
            y.w = tanh_fast(acc[1][2 * h + 1] + br0.w);
            op[0] = y;
            y.x = tanh_fast(acc[2][2 * h]     + br1.x);
            y.y = tanh_fast(acc[2][2 * h + 1] + br1.y);
            y.z = tanh_fast(acc[3][2 * h]     + br1.z);
            y.w = tanh_fast(acc[3][2 * h + 1] + br1.w);
            op[1] = y;
            y.x = tanh_fast(acc[4][2 * h]     + br2.x);
            y.y = tanh_fast(acc[4][2 * h + 1] + br2.y);
            y.z = tanh_fast(acc[5][2 * h]     + br2.z);
            y.w = tanh_fast(acc[5][2 * h + 1] + br2.w);
            op[2] = y;
            y.x = tanh_fast(acc[6][2 * h]     + br3.x);
            y.y = tanh_fast(acc[6][2 * h + 1] + br3.y);
            y.z = tanh_fast(acc[7][2 * h]     + br3.z);
            y.w = tanh_fast(acc[7][2 * h + 1] + br3.w);
            op[3] = y;
        }
        __syncthreads();   // protect sp/smem before next stride iteration
    }
}

// -------------------------------------------------------------- launch ----
extern "C" void kernel_launch(void* const* d_in, const int* in_sizes, int n_in,
                              void* d_out, int out_size)
{
    const float* x   = (const float*)d_in[0];
    const int*   ty  = (const int*)d_in[1];
    const float* W   = (const float*)d_in[2];
    const float* b   = (const float*)d_in[3];
    float*       out = (float*)d_out;

    const int n = in_sizes[0] / D;

    static bool attr_set = false;
    if (!attr_set) {
        cudaFuncSetAttribute(k_compute,
                             cudaFuncAttributeMaxDynamicSharedMemorySize,
                             SM_TOTAL);
        attr_set = true;
    }

    k_bucket<<<BBLK, 256>>>(ty, n);
    dim3 grid(256, MAX_TILES);
    k_compute<<<grid, 256, SM_TOTAL>>>(x, W, b, out);
}

// round 15
// speedup vs baseline: 1.0636x; 1.0636x over previous
#include <cuda_runtime.h>
#include <cuda_bf16.h>
#include <cstdint>

// y[n] = tanh(W[t_n] @ x[n] + b[t_n]);  N=131072, D=64, 256 types (int32).
// 1) k_bucket: single-pass bucketing by type (block-aggregated atomics).
// 2) k_compute: per (type, 128-atom tile) CTA, 256 threads, HMMA bf16
//    m16n8k16 with split-bf16 (hi+lo, 3 chained MMAs), ldmatrix loads.
//    W columns are PERMUTED at staging so each thread owns 16 contiguous
//    output columns -> epilogue is STG.128s with optimal sectors.
// Flat structure (one tile per CTA, early return) keeps regs ~58 / occ ~47%.
// Counters self-reset (last CTA per type) -> state all-zero every replay.

#define D 64
#define MAX_N 131072
#define TILE 128
#define CAP 1024
#define MAX_TILES 8
#define BBLK 256
#define XPB 144   // smem pitch bytes; 144%128==16 -> ldmatrix conflict-free

__device__ int g_cnt[256];
__device__ int g_done[256];
__device__ int g_perm[256 * CAP];

// ------------------------------------------------------------------ sort ----
__global__ void k_bucket(const int* __restrict__ types, int n)
{
    __shared__ int sh_cnt[256];
    __shared__ int sh_base[256];
    const int g = blockIdx.x, tid = threadIdx.x;
    sh_cnt[tid] = 0;
    __syncthreads();

    const int chunk = (n + BBLK - 1) / BBLK;
    const int lo = g * chunk, hi = min(n, lo + chunk);

    int tcache[4];
    int cnt = 0;
    for (int i = lo + tid; i < hi; i += blockDim.x) {
        int t = types[i] & 255;
        tcache[cnt++] = t;
        atomicAdd(&sh_cnt[t], 1);
    }
    __syncthreads();

    const int c = sh_cnt[tid];
    sh_base[tid] = tid * CAP + ((c > 0) ? atomicAdd(&g_cnt[tid], c) : 0);
    __syncthreads();

    cnt = 0;
    for (int i = lo + tid; i < hi; i += blockDim.x) {
        int t = tcache[cnt++];
        int dst = atomicAdd(&sh_base[t], 1);
        g_perm[dst] = i;
    }
}

// --------------------------------------------------------------- helpers ----
__device__ __forceinline__ uint32_t smem_u32(const void* p) {
    uint32_t a;
    asm("{ .reg .u64 t; cvta.to.shared.u64 t, %1; cvt.u32.u64 %0, t; }"
        : "=r"(a) : "l"(p));
    return a;
}
__device__ __forceinline__ float tanh_fast(float x) {
    float r;
    asm("tanh.approx.f32 %0, %1;" : "=f"(r) : "f"(x));
    return r;
}
__device__ __forceinline__ void ldsm4(uint32_t* r, uint32_t addr) {
    asm volatile("ldmatrix.sync.aligned.m8n8.x4.shared.b16 {%0,%1,%2,%3}, [%4];"
                 : "=r"(r[0]), "=r"(r[1]), "=r"(r[2]), "=r"(r[3]) : "r"(addr));
}
__device__ __forceinline__ void mma16816(float* c, const uint32_t* a,
                                         uint32_t b0, uint32_t b1)
{
    asm volatile(
        "mma.sync.aligned.m16n8k16.row.col.f32.bf16.bf16.f32 "
        "{%0,%1,%2,%3}, {%4,%5,%6,%7}, {%8,%9}, {%0,%1,%2,%3};"
        : "+f"(c[0]), "+f"(c[1]), "+f"(c[2]), "+f"(c[3])
        : "r"(a[0]), "r"(a[1]), "r"(a[2]), "r"(a[3]), "r"(b0), "r"(b1));
}
__device__ __forceinline__ void cvt_split(float4 v, uint2& hi, uint2& lo)
{
    __nv_bfloat162 h01 = __floats2bfloat162_rn(v.x, v.y);
    __nv_bfloat162 h23 = __floats2bfloat162_rn(v.z, v.w);
    __nv_bfloat162 l01 = __floats2bfloat162_rn(
        v.x - __bfloat162float(h01.x), v.y - __bfloat162float(h01.y));
    __nv_bfloat162 l23 = __floats2bfloat162_rn(
        v.z - __bfloat162float(h23.x), v.w - __bfloat162float(h23.y));
    hi = make_uint2(*(uint32_t*)&h01, *(uint32_t*)&h23);
    lo = make_uint2(*(uint32_t*)&l01, *(uint32_t*)&l23);
}

// ------------------------------------------------------------- compute ----
#define SM_SP    0
#define SM_XHI   768
#define SM_XLO   (SM_XHI + TILE * XPB)
#define SM_WHI   (SM_XLO + TILE * XPB)
#define SM_WLO   (SM_WHI + 64 * XPB)
#define SM_TOTAL (SM_WLO + 64 * XPB)     // 56064 bytes
#define DXL      (SM_XLO - SM_XHI)
#define DWL      (SM_WLO - SM_WHI)

__global__ __launch_bounds__(256)
void k_compute(const float* __restrict__ x,
               const float* __restrict__ W,
               const float* __restrict__ b,
               float* __restrict__ out)
{
    extern __shared__ char smem[];
    const int t    = blockIdx.x;
    const int tile = blockIdx.y;
    const int tid  = threadIdx.x;

    // Read this type's count; last CTA of the type resets counters.
    __shared__ int s_end;
    if (tid == 0) {
        int e = *((volatile int*)&g_cnt[t]);
        __threadfence();
        if (atomicAdd(&g_done[t], 1) == MAX_TILES - 1) {
            g_done[t] = 0;
            g_cnt[t]  = 0;
            __threadfence();
        }
        s_end = e;
    }
    __syncthreads();
    const int cnt_t  = s_end;
    const int base_l = tile * TILE;
    if (base_l >= cnt_t) return;

    int* sp = (int*)(smem + SM_SP);

    if (tid < TILE)
        sp[tid] = (base_l + tid < cnt_t) ? g_perm[t * CAP + base_l + tid] : -1;
    __syncthreads();

    // Stage X tile (fp32 -> bf16 hi+lo), pitch 144B.
#pragma unroll
    for (int i = 0; i < 8; i++) {
        int idx = tid + i * 256;
        int row = idx >> 4, c4 = idx & 15;
        int a = sp[row];
        if (a >= 0) {
            float4 v = reinterpret_cast<const float4*>(x + (size_t)a * D)[c4];
            uint2 hi, lo;
            cvt_split(v, hi, lo);
            char* p = smem + SM_XHI + row * XPB + c4 * 8;
            *(uint2*)p         = hi;
            *(uint2*)(p + DXL) = lo;
        }
    }
    // Stage W[t] with column permutation: gmem W row o -> smem row
    // rW = 8*((o&15)>>1) + 2*(o>>4) + (o&1), so the MMA n-index maps
    // thread tig to output cols [16*tig, 16*tig+16).
    const float4* Wt = reinterpret_cast<const float4*>(W + (size_t)t * D * D);
#pragma unroll
    for (int i = 0; i < 4; i++) {
        int idx = tid + i * 256;
        int o = idx >> 4, c4 = idx & 15;
        int rW = 8 * ((o & 15) >> 1) + 2 * (o >> 4) + (o & 1);
        uint2 hi, lo;
        cvt_split(Wt[idx], hi, lo);
        char* p = smem + SM_WHI + rW * XPB + c4 * 8;
        *(uint2*)p         = hi;
        *(uint2*)(p + DWL) = lo;
    }
    __syncthreads();

    const int wid = tid >> 5, lane = tid & 31;
    const int gq = lane >> 2, tig = lane & 3;
    const uint32_t sb = smem_u32(smem);

    const uint32_t aAddr = sb + SM_XHI +
        (wid * 16 + (lane & 7) + ((lane >> 3) & 1) * 8) * XPB +
        ((lane >> 4) & 1) * 16;
    const uint32_t bAddr = sb + SM_WHI +
        ((lane & 7) + ((lane >> 4) & 1) * 8) * XPB +
        ((lane >> 3) & 1) * 16;

    float acc[8][4];
#pragma unroll
    for (int nt = 0; nt < 8; nt++)
#pragma unroll
        for (int r = 0; r < 4; r++) acc[nt][r] = 0.f;

#pragma unroll
    for (int k = 0; k < 4; k++) {
        uint32_t ah[4], al[4];
        ldsm4(ah, aAddr + k * 32);
        ldsm4(al, aAddr + k * 32 + DXL);
#pragma unroll
        for (int p = 0; p < 4; p++) {
            uint32_t bh[4], bl[4];
            uint32_t pb = bAddr + p * (16 * XPB) + k * 32;
            ldsm4(bh, pb);
            ldsm4(bl, pb + DWL);
            mma16816(acc[2 * p],     ah, bh[0], bh[1]);
            mma16816(acc[2 * p],     al, bh[0], bh[1]);
            mma16816(acc[2 * p],     ah, bl[0], bl[1]);
            mma16816(acc[2 * p + 1], ah, bh[2], bh[3]);
            mma16816(acc[2 * p + 1], al, bh[2], bh[3]);
            mma16816(acc[2 * p + 1], ah, bl[2], bl[3]);
        }
    }

    // Epilogue: thread owns output cols [16*tig, 16*tig+16).
    // acc[nt][2h+e] = (row wid*16 + h*8 + gq, col 16*tig + 2*nt + e).
    // Bias read directly (warp-uniform line, L2/L1 hit).
    const float4* bb = reinterpret_cast<const float4*>(b + (size_t)t * D + 16 * tig);
    const float4 br0 = bb[0], br1 = bb[1], br2 = bb[2], br3 = bb[3];
#pragma unroll
    for (int h = 0; h < 2; h++) {
        const int r = wid * 16 + h * 8 + gq;
        const int a = sp[r];
        if (a < 0) continue;
        float4* op = reinterpret_cast<float4*>(out + (size_t)a * D + 16 * tig);
        float4 y;
        y.x = tanh_fast(acc[0][2 * h]     + br0.x);
        y.y = tanh_fast(acc[0][2 * h + 1] + br0.y);
        y.z = tanh_fast(acc[1][2 * h]     + br0.z);
        y.w = tanh_fast(acc[1][2 * h + 1] + br0.w);
        op[0] = y;
        y.x = tanh_fast(acc[2][2 * h]     + br1.x);
        y.y = tanh_fast(acc[2][2 * h + 1] + br1.y);
        y.z = tanh_fast(acc[3][2 * h]     + br1.z);
        y.w = tanh_fast(acc[3][2 * h + 1] + br1.w);
        op[1] = y;
        y.x = tanh_fast(acc[4][2 * h]     + br2.x);
        y.y = tanh_fast(acc[4][2 * h + 1] + br2.y);
        y.z = tanh_fast(acc[5][2 * h]     + br2.z);
        y.w = tanh_fast(acc[5][2 * h + 1] + br2.w);
        op[2] = y;
        y.x = tanh_fast(acc[6][2 * h]     + br3.x);
        y.y = tanh_fast(acc[6][2 * h + 1] + br3.y);
        y.z = tanh_fast(acc[7][2 * h]     + br3.z);
        y.w = tanh_fast(acc[7][2 * h + 1] + br3.w);
        op[3] = y;
    }
}

// -------------------------------------------------------------- launch ----
extern "C" void kernel_launch(void* const* d_in, const int* in_sizes, int n_in,
                              void* d_out, int out_size)
{
    const float* x   = (const float*)d_in[0];
    const int*   ty  = (const int*)d_in[1];
    const float* W   = (const float*)d_in[2];
    const float* b   = (const float*)d_in[3];
    float*       out = (float*)d_out;

    const int n = in_sizes[0] / D;

    static bool attr_set = false;
    if (!attr_set) {
        cudaFuncSetAttribute(k_compute,
                             cudaFuncAttributeMaxDynamicSharedMemorySize,
                             SM_TOTAL);
        attr_set = true;
    }

    k_bucket<<<BBLK, 256>>>(ty, n);
    dim3 grid(256, MAX_TILES);
    k_compute<<<grid, 256, SM_TOTAL>>>(x, W, b, out);
}

// round 16
// speedup vs baseline: 1.0697x; 1.0057x over previous
#include <cuda_runtime.h>
#include <cuda_bf16.h>
#include <cstdint>

// y[n] = tanh(W[t_n] @ x[n] + b[t_n]);  N=131072, D=64, 256 types (int32).
// 1) k_bucket: single-pass bucketing by type (block-aggregated atomics).
// 2) k_compute: per (type, 128-atom tile) CTA, 256 threads, HMMA bf16
//    m16n8k16 with split-bf16 (hi+lo, 3 chained MMAs), ldmatrix loads.
//    W columns permuted at staging -> each thread owns 16 contiguous output
//    columns -> epilogue is STG.128s.  __launch_bounds__(256,4) pins the
//    allocation at <=64 regs so 4 CTAs/SM fit (the 66-reg/3-CTA cliff cost
//    R14/R15 ~8us).
// Counters self-reset (last CTA per type) -> state all-zero every replay.

#define D 64
#define MAX_N 131072
#define TILE 128
#define CAP 1024
#define MAX_TILES 8
#define BBLK 256
#define XPB 144   // smem pitch bytes; 144%128==16 -> ldmatrix conflict-free

__device__ int g_cnt[256];
__device__ int g_done[256];
__device__ int g_perm[256 * CAP];

// ------------------------------------------------------------------ sort ----
__global__ void k_bucket(const int* __restrict__ types, int n)
{
    __shared__ int sh_cnt[256];
    __shared__ int sh_base[256];
    const int g = blockIdx.x, tid = threadIdx.x;
    sh_cnt[tid] = 0;
    __syncthreads();

    const int chunk = (n + BBLK - 1) / BBLK;
    const int lo = g * chunk, hi = min(n, lo + chunk);

    int tcache[4];
    int cnt = 0;
    for (int i = lo + tid; i < hi; i += blockDim.x) {
        int t = types[i] & 255;
        tcache[cnt++] = t;
        atomicAdd(&sh_cnt[t], 1);
    }
    __syncthreads();

    const int c = sh_cnt[tid];
    sh_base[tid] = tid * CAP + ((c > 0) ? atomicAdd(&g_cnt[tid], c) : 0);
    __syncthreads();

    cnt = 0;
    for (int i = lo + tid; i < hi; i += blockDim.x) {
        int t = tcache[cnt++];
        int dst = atomicAdd(&sh_base[t], 1);
        g_perm[dst] = i;
    }
}

// --------------------------------------------------------------- helpers ----
__device__ __forceinline__ uint32_t smem_u32(const void* p) {
    uint32_t a;
    asm("{ .reg .u64 t; cvta.to.shared.u64 t, %1; cvt.u32.u64 %0, t; }"
        : "=r"(a) : "l"(p));
    return a;
}
__device__ __forceinline__ float tanh_fast(float x) {
    float r;
    asm("tanh.approx.f32 %0, %1;" : "=f"(r) : "f"(x));
    return r;
}
__device__ __forceinline__ void ldsm4(uint32_t* r, uint32_t addr) {
    asm volatile("ldmatrix.sync.aligned.m8n8.x4.shared.b16 {%0,%1,%2,%3}, [%4];"
                 : "=r"(r[0]), "=r"(r[1]), "=r"(r[2]), "=r"(r[3]) : "r"(addr));
}
__device__ __forceinline__ void mma16816(float* c, const uint32_t* a,
                                         uint32_t b0, uint32_t b1)
{
    asm volatile(
        "mma.sync.aligned.m16n8k16.row.col.f32.bf16.bf16.f32 "
        "{%0,%1,%2,%3}, {%4,%5,%6,%7}, {%8,%9}, {%0,%1,%2,%3};"
        : "+f"(c[0]), "+f"(c[1]), "+f"(c[2]), "+f"(c[3])
        : "r"(a[0]), "r"(a[1]), "r"(a[2]), "r"(a[3]), "r"(b0), "r"(b1));
}
__device__ __forceinline__ void cvt_split(float4 v, uint2& hi, uint2& lo)
{
    __nv_bfloat162 h01 = __floats2bfloat162_rn(v.x, v.y);
    __nv_bfloat162 h23 = __floats2bfloat162_rn(v.z, v.w);
    __nv_bfloat162 l01 = __floats2bfloat162_rn(
        v.x - __bfloat162float(h01.x), v.y - __bfloat162float(h01.y));
    __nv_bfloat162 l23 = __floats2bfloat162_rn(
        v.z - __bfloat162float(h23.x), v.w - __bfloat162float(h23.y));
    hi = make_uint2(*(uint32_t*)&h01, *(uint32_t*)&h23);
    lo = make_uint2(*(uint32_t*)&l01, *(uint32_t*)&l23);
}

// ------------------------------------------------------------- compute ----
#define SM_SP    0
#define SM_XHI   768
#define SM_XLO   (SM_XHI + TILE * XPB)
#define SM_WHI   (SM_XLO + TILE * XPB)
#define SM_WLO   (SM_WHI + 64 * XPB)
#define SM_TOTAL (SM_WLO + 64 * XPB)     // 56064 bytes
#define DXL      (SM_XLO - SM_XHI)
#define DWL      (SM_WLO - SM_WHI)

__global__ __launch_bounds__(256, 4)
void k_compute(const float* __restrict__ x,
               const float* __restrict__ W,
               const float* __restrict__ b,
               float* __restrict__ out)
{
    extern __shared__ char smem[];
    const int t    = blockIdx.x;
    const int tile = blockIdx.y;
    const int tid  = threadIdx.x;

    // Read this type's count; last CTA of the type resets counters.
    __shared__ int s_end;
    if (tid == 0) {
        int e = *((volatile int*)&g_cnt[t]);
        __threadfence();
        if (atomicAdd(&g_done[t], 1) == MAX_TILES - 1) {
            g_done[t] = 0;
            g_cnt[t]  = 0;
            __threadfence();
        }
        s_end = e;
    }
    __syncthreads();
    const int cnt_t  = s_end;
    const int base_l = tile * TILE;
    if (base_l >= cnt_t) return;

    int* sp = (int*)(smem + SM_SP);

    if (tid < TILE)
        sp[tid] = (base_l + tid < cnt_t) ? g_perm[t * CAP + base_l + tid] : -1;
    __syncthreads();

    // Stage X tile (fp32 -> bf16 hi+lo), pitch 144B.
#pragma unroll
    for (int i = 0; i < 8; i++) {
        int idx = tid + i * 256;
        int row = idx >> 4, c4 = idx & 15;
        int a = sp[row];
        if (a >= 0) {
            float4 v = reinterpret_cast<const float4*>(x + (size_t)a * D)[c4];
            uint2 hi, lo;
            cvt_split(v, hi, lo);
            char* p = smem + SM_XHI + row * XPB + c4 * 8;
            *(uint2*)p         = hi;
            *(uint2*)(p + DXL) = lo;
        }
    }
    // Stage W[t] with column permutation: gmem W row o -> smem row
    // rW = 8*((o&15)>>1) + 2*(o>>4) + (o&1), so the MMA n-index maps
    // thread tig to output cols [16*tig, 16*tig+16).
    const float4* Wt = reinterpret_cast<const float4*>(W + (size_t)t * D * D);
#pragma unroll
    for (int i = 0; i < 4; i++) {
        int idx = tid + i * 256;
        int o = idx >> 4, c4 = idx & 15;
        int rW = 8 * ((o & 15) >> 1) + 2 * (o >> 4) + (o & 1);
        uint2 hi, lo;
        cvt_split(Wt[idx], hi, lo);
        char* p = smem + SM_WHI + rW * XPB + c4 * 8;
        *(uint2*)p         = hi;
        *(uint2*)(p + DWL) = lo;
    }
    __syncthreads();

    const int wid = tid >> 5, lane = tid & 31;
    const int gq = lane >> 2, tig = lane & 3;
    const uint32_t sb = smem_u32(smem);

    const uint32_t aAddr = sb + SM_XHI +
        (wid * 16 + (lane & 7) + ((lane >> 3) & 1) * 8) * XPB +
        ((lane >> 4) & 1) * 16;
    const uint32_t bAddr = sb + SM_WHI +
        ((lane & 7) + ((lane >> 4) & 1) * 8) * XPB +
        ((lane >> 3) & 1) * 16;

    float acc[8][4];
#pragma unroll
    for (int nt = 0; nt < 8; nt++)
#pragma unroll
        for (int r = 0; r < 4; r++) acc[nt][r] = 0.f;

#pragma unroll
    for (int k = 0; k < 4; k++) {
        uint32_t ah[4], al[4];
        ldsm4(ah, aAddr + k * 32);
        ldsm4(al, aAddr + k * 32 + DXL);
#pragma unroll
        for (int p = 0; p < 4; p++) {
            uint32_t bh[4], bl[4];
            uint32_t pb = bAddr + p * (16 * XPB) + k * 32;
            ldsm4(bh, pb);
            ldsm4(bl, pb + DWL);
            mma16816(acc[2 * p],     ah, bh[0], bh[1]);
            mma16816(acc[2 * p],     al, bh[0], bh[1]);
            mma16816(acc[2 * p],     ah, bl[0], bl[1]);
            mma16816(acc[2 * p + 1], ah, bh[2], bh[3]);
            mma16816(acc[2 * p + 1], al, bh[2], bh[3]);
            mma16816(acc[2 * p + 1], ah, bl[2], bl[3]);
        }
    }

    // Epilogue: thread owns output cols [16*tig, 16*tig+16).
    // acc[nt][2h+e] = (row wid*16 + h*8 + gq, col 16*tig + 2*nt + e).
    const float* bp = b + (size_t)t * D + 16 * tig;   // warp-uniform line
#pragma unroll
    for (int h = 0; h < 2; h++) {
        const int r = wid * 16 + h * 8 + gq;
        const int a = sp[r];
        if (a < 0) continue;
        float4* op = reinterpret_cast<float4*>(out + (size_t)a * D + 16 * tig);
#pragma unroll
        for (int q = 0; q < 4; q++) {
            const float4 br = reinterpret_cast<const float4*>(bp)[q];
            float4 y;
            y.x = tanh_fast(acc[2 * q][2 * h]         + br.x);
            y.y = tanh_fast(acc[2 * q][2 * h + 1]     + br.y);
            y.z = tanh_fast(acc[2 * q + 1][2 * h]     + br.z);
            y.w = tanh_fast(acc[2 * q + 1][2 * h + 1] + br.w);
            op[q] = y;
        }
    }
}

// -------------------------------------------------------------- launch ----
extern "C" void kernel_launch(void* const* d_in, const int* in_sizes, int n_in,
                              void* d_out, int out_size)
{
    const float* x   = (const float*)d_in[0];
    const int*   ty  = (const int*)d_in[1];
    const float* W   = (const float*)d_in[2];
    const float* b   = (const float*)d_in[3];
    float*       out = (float*)d_out;

    const int n = in_sizes[0] / D;

    static bool attr_set = false;
    if (!attr_set) {
        cudaFuncSetAttribute(k_compute,
                             cudaFuncAttributeMaxDynamicSharedMemorySize,
                             SM_TOTAL);
        attr_set = true;
    }

    k_bucket<<<BBLK, 256>>>(ty, n);
    dim3 grid(256, MAX_TILES);
    k_compute<<<grid, 256, SM_TOTAL>>>(x, W, b, out);
}

// round 17
// speedup vs baseline: 1.1133x; 1.0408x over previous
#include <cuda_runtime.h>
#include <cuda_bf16.h>
#include <cstdint>

// y[n] = tanh(W[t_n] @ x[n] + b[t_n]);  N=131072, D=64, 256 types (int32).
// 1) k_bucket: single-pass bucketing by type (block-aggregated atomics).
// 2) k_compute: per (type, 256-atom tile) CTA, 512 threads / 16 warps.
//    Each warp: 16 rows x 64 cols via HMMA bf16 m16n8k16, split-bf16
//    (hi+lo, 3 chained MMAs), ldmatrix loads, scattered-float2 epilogue
//    (proven faster than STG.128 permute: sector packing).
//    TILE=256 amortizes W convert/stage + counter logic over 2x atoms.
// Counters self-reset (last CTA per type) -> state all-zero every replay.

#define D 64
#define MAX_N 131072
#define TILE 256
#define CAP 1024
#define MAX_TILES 3       // 768 slots; type counts are 512 +/- 23 (max ~580)
#define BBLK 256
#define XPB 144   // smem pitch bytes; 144%128==16 -> ldmatrix conflict-free

__device__ int g_cnt[256];
__device__ int g_done[256];
__device__ int g_perm[256 * CAP];

// ------------------------------------------------------------------ sort ----
__global__ void k_bucket(const int* __restrict__ types, int n)
{
    __shared__ int sh_cnt[256];
    __shared__ int sh_base[256];
    const int g = blockIdx.x, tid = threadIdx.x;
    sh_cnt[tid] = 0;
    __syncthreads();

    const int chunk = (n + BBLK - 1) / BBLK;
    const int lo = g * chunk, hi = min(n, lo + chunk);

    int tcache[4];
    int cnt = 0;
    for (int i = lo + tid; i < hi; i += blockDim.x) {
        int t = types[i] & 255;
        tcache[cnt++] = t;
        atomicAdd(&sh_cnt[t], 1);
    }
    __syncthreads();

    const int c = sh_cnt[tid];
    sh_base[tid] = tid * CAP + ((c > 0) ? atomicAdd(&g_cnt[tid], c) : 0);
    __syncthreads();

    cnt = 0;
    for (int i = lo + tid; i < hi; i += blockDim.x) {
        int t = tcache[cnt++];
        int dst = atomicAdd(&sh_base[t], 1);
        g_perm[dst] = i;
    }
}

// --------------------------------------------------------------- helpers ----
__device__ __forceinline__ uint32_t smem_u32(const void* p) {
    uint32_t a;
    asm("{ .reg .u64 t; cvta.to.shared.u64 t, %1; cvt.u32.u64 %0, t; }"
        : "=r"(a) : "l"(p));
    return a;
}
__device__ __forceinline__ float tanh_fast(float x) {
    float r;
    asm("tanh.approx.f32 %0, %1;" : "=f"(r) : "f"(x));
    return r;
}
__device__ __forceinline__ void ldsm4(uint32_t* r, uint32_t addr) {
    asm volatile("ldmatrix.sync.aligned.m8n8.x4.shared.b16 {%0,%1,%2,%3}, [%4];"
                 : "=r"(r[0]), "=r"(r[1]), "=r"(r[2]), "=r"(r[3]) : "r"(addr));
}
__device__ __forceinline__ void mma16816(float* c, const uint32_t* a,
                                         uint32_t b0, uint32_t b1)
{
    asm volatile(
        "mma.sync.aligned.m16n8k16.row.col.f32.bf16.bf16.f32 "
        "{%0,%1,%2,%3}, {%4,%5,%6,%7}, {%8,%9}, {%0,%1,%2,%3};"
        : "+f"(c[0]), "+f"(c[1]), "+f"(c[2]), "+f"(c[3])
        : "r"(a[0]), "r"(a[1]), "r"(a[2]), "r"(a[3]), "r"(b0), "r"(b1));
}
__device__ __forceinline__ void cvt_split(float4 v, uint2& hi, uint2& lo)
{
    __nv_bfloat162 h01 = __floats2bfloat162_rn(v.x, v.y);
    __nv_bfloat162 h23 = __floats2bfloat162_rn(v.z, v.w);
    __nv_bfloat162 l01 = __floats2bfloat162_rn(
        v.x - __bfloat162float(h01.x), v.y - __bfloat162float(h01.y));
    __nv_bfloat162 l23 = __floats2bfloat162_rn(
        v.z - __bfloat162float(h23.x), v.w - __bfloat162float(h23.y));
    hi = make_uint2(*(uint32_t*)&h01, *(uint32_t*)&h23);
    lo = make_uint2(*(uint32_t*)&l01, *(uint32_t*)&l23);
}

// ------------------------------------------------------------- compute ----
#define SM_SP    0                          // 256 ints
#define SM_BIAS  1024                       // 64 floats
#define SM_XHI   1280
#define SM_XLO   (SM_XHI + TILE * XPB)      // +36864
#define SM_WHI   (SM_XLO + TILE * XPB)
#define SM_WLO   (SM_WHI + 64 * XPB)        // +9216
#define SM_TOTAL (SM_WLO + 64 * XPB)        // 93440 bytes
#define DXL      (SM_XLO - SM_XHI)
#define DWL      (SM_WLO - SM_WHI)

__global__ __launch_bounds__(512, 2)
void k_compute(const float* __restrict__ x,
               const float* __restrict__ W,
               const float* __restrict__ b,
               float* __restrict__ out)
{
    extern __shared__ char smem[];
    const int t    = blockIdx.x;
    const int tile = blockIdx.y;
    const int tid  = threadIdx.x;

    // Read this type's count; last CTA of the type resets counters.
    __shared__ int s_end;
    if (tid == 0) {
        int e = *((volatile int*)&g_cnt[t]);
        __threadfence();
        if (atomicAdd(&g_done[t], 1) == MAX_TILES - 1) {
            g_done[t] = 0;
            g_cnt[t]  = 0;
            __threadfence();
        }
        s_end = e;
    }
    __syncthreads();
    const int cnt_t  = s_end;
    const int base_l = tile * TILE;
    if (base_l >= cnt_t) return;

    int*   sp    = (int*)(smem + SM_SP);
    float* sbias = (float*)(smem + SM_BIAS);

    if (tid < TILE)
        sp[tid] = (base_l + tid < cnt_t) ? g_perm[t * CAP + base_l + tid] : -1;
    if (tid >= 448) sbias[tid - 448] = b[(size_t)t * 64 + (tid - 448)];
    __syncthreads();

    // Stage X tile (fp32 -> bf16 hi+lo), pitch 144B.  4096 float4 slots.
#pragma unroll
    for (int i = 0; i < 8; i++) {
        int idx = tid + i * 512;
        int row = idx >> 4, c4 = idx & 15;
        int a = sp[row];
        if (a >= 0) {
            float4 v = reinterpret_cast<const float4*>(x + (size_t)a * D)[c4];
            uint2 hi, lo;
            cvt_split(v, hi, lo);
            char* p = smem + SM_XHI + row * XPB + c4 * 8;
            *(uint2*)p         = hi;
            *(uint2*)(p + DXL) = lo;
        }
    }
    // Stage W[t] (64x64) split.  1024 float4 slots.
    const float4* Wt = reinterpret_cast<const float4*>(W + (size_t)t * D * D);
#pragma unroll
    for (int i = 0; i < 2; i++) {
        int idx = tid + i * 512;
        int row = idx >> 4, c4 = idx & 15;
        uint2 hi, lo;
        cvt_split(Wt[idx], hi, lo);
        char* p = smem + SM_WHI + row * XPB + c4 * 8;
        *(uint2*)p         = hi;
        *(uint2*)(p + DWL) = lo;
    }
    __syncthreads();

    const int wid = tid >> 5, lane = tid & 31;
    const int gq = lane >> 2, tig = lane & 3;
    const uint32_t sb = smem_u32(smem);

    const uint32_t aAddr = sb + SM_XHI +
        (wid * 16 + (lane & 7) + ((lane >> 3) & 1) * 8) * XPB +
        ((lane >> 4) & 1) * 16;
    const uint32_t bAddr = sb + SM_WHI +
        ((lane & 7) + ((lane >> 4) & 1) * 8) * XPB +
        ((lane >> 3) & 1) * 16;

    float acc[8][4];
#pragma unroll
    for (int nt = 0; nt < 8; nt++)
#pragma unroll
        for (int r = 0; r < 4; r++) acc[nt][r] = 0.f;

#pragma unroll
    for (int k = 0; k < 4; k++) {
        uint32_t ah[4], al[4];
        ldsm4(ah, aAddr + k * 32);
        ldsm4(al, aAddr + k * 32 + DXL);
#pragma unroll
        for (int p = 0; p < 4; p++) {
            uint32_t bh[4], bl[4];
            uint32_t pb = bAddr + p * (16 * XPB) + k * 32;
            ldsm4(bh, pb);
            ldsm4(bl, pb + DWL);
            mma16816(acc[2 * p],     ah, bh[0], bh[1]);
            mma16816(acc[2 * p],     al, bh[0], bh[1]);
            mma16816(acc[2 * p],     ah, bl[0], bl[1]);
            mma16816(acc[2 * p + 1], ah, bh[2], bh[3]);
            mma16816(acc[2 * p + 1], al, bh[2], bh[3]);
            mma16816(acc[2 * p + 1], ah, bl[2], bl[3]);
        }
    }

    // Epilogue (R11 pattern): bias via smem, scattered float2 stores.
    float br[16];
#pragma unroll
    for (int nt = 0; nt < 8; nt++) {
        br[2 * nt]     = sbias[8 * nt + 2 * tig];
        br[2 * nt + 1] = sbias[8 * nt + 2 * tig + 1];
    }
#pragma unroll
    for (int h = 0; h < 2; h++) {
        const int r = wid * 16 + h * 8 + gq;
        const int a = sp[r];
        if (a < 0) continue;
        float* orow = out + (size_t)a * D;
#pragma unroll
        for (int nt = 0; nt < 8; nt++) {
            float2 y;
            y.x = tanh_fast(acc[nt][2 * h]     + br[2 * nt]);
            y.y = tanh_fast(acc[nt][2 * h + 1] + br[2 * nt + 1]);
            *(float2*)(orow + 8 * nt + 2 * tig) = y;
        }
    }
}

// -------------------------------------------------------------- launch ----
extern "C" void kernel_launch(void* const* d_in, const int* in_sizes, int n_in,
                              void* d_out, int out_size)
{
    const float* x   = (const float*)d_in[0];
    const int*   ty  = (const int*)d_in[1];
    const float* W   = (const float*)d_in[2];
    const float* b   = (const float*)d_in[3];
    float*       out = (float*)d_out;

    const int n = in_sizes[0] / D;

    static bool attr_set = false;
    if (!attr_set) {
        cudaFuncSetAttribute(k_compute,
                             cudaFuncAttributeMaxDynamicSharedMemorySize,
                             SM_TOTAL);
        attr_set = true;
    }

    k_bucket<<<BBLK, 256>>>(ty, n);
    dim3 grid(256, MAX_TILES);
    k_compute<<<grid, 512, SM_TOTAL>>>(x, W, b, out);
}